// round 1
// baseline (speedup 1.0000x reference)
#include <cuda_runtime.h>
#include <math.h>

// Problem constants (from reference: N=8192, C=5000, RATIO=3.0)
#define NC        5000
#define NTHREADS  256
#define NWARPS    8
#define NWORDS    157   // ceil(5000/32) target bitmask words

__device__ double g_loss;
__device__ double g_tsum;

// order-preserving float -> uint key (larger float <-> larger key)
__device__ __forceinline__ unsigned fkey(float f) {
    unsigned b = __float_as_uint(f);
    return (b & 0x80000000u) ? ~b : (b | 0x80000000u);
}
__device__ __forceinline__ float kinv(unsigned k) {
    return __uint_as_float((k & 0x80000000u) ? (k & 0x7FFFFFFFu) : ~k);
}

// numerically stable softplus
__device__ __forceinline__ float softplusf(float x) {
    float r = log1pf(__expf(-fabsf(x)));
    return x > 0.f ? x + r : r;
}

__global__ void __launch_bounds__(NTHREADS)
hardneg_kernel(const float* __restrict__ pred, const float* __restrict__ target) {
    __shared__ float    s_pred[NC];
    __shared__ unsigned s_tbits[NWORDS];
    __shared__ unsigned s_hist[NWARPS][256];
    __shared__ unsigned s_cnt[256];
    __shared__ unsigned s_scan[256];
    __shared__ unsigned s_bsel, s_krem;
    __shared__ int      s_pos;
    __shared__ float    s_red[NWARPS];

    const int row  = blockIdx.x;
    const int tid  = threadIdx.x;
    const int wid  = tid >> 5;
    const int lane = tid & 31;

    const float* prow = pred   + (size_t)row * NC;
    const float* trow = target + (size_t)row * NC;

    // ---- load pred row (vectorized: 5000 = 1250 * float4) ----
    const float4* p4 = (const float4*)prow;
    #pragma unroll 2
    for (int i = tid; i < NC / 4; i += NTHREADS) {
        float4 v = p4[i];
        s_pred[4 * i + 0] = v.x;
        s_pred[4 * i + 1] = v.y;
        s_pred[4 * i + 2] = v.z;
        s_pred[4 * i + 3] = v.w;
    }

    // ---- target -> bitmask via warp ballot (coalesced) ----
    for (int wdx = wid; wdx < NWORDS; wdx += NWARPS) {
        int idx = wdx * 32 + lane;
        float t = (idx < NC) ? trow[idx] : 0.f;
        unsigned m = __ballot_sync(0xFFFFFFFFu, t != 0.f);
        if (lane == 0) s_tbits[wdx] = m;
    }
    __syncthreads();

    // ---- positive count ----
    {
        int pc = 0;
        for (int w = tid; w < NWORDS; w += NTHREADS) pc += __popc(s_tbits[w]);
        #pragma unroll
        for (int o = 16; o; o >>= 1) pc += __shfl_down_sync(0xFFFFFFFFu, pc, o);
        if (lane == 0) s_red[wid] = __int_as_float(pc);
        __syncthreads();
        if (tid == 0) {
            int tot = 0;
            for (int w = 0; w < NWARPS; w++) tot += __float_as_int(s_red[w]);
            s_pos = tot;
        }
        __syncthreads();
    }

    const int pos = s_pos;
    int k0 = 3 * pos;
    if (k0 > NC - pos) k0 = NC - pos;   // k = min(3*pos, C - pos)

    // ---- 4-round radix select: exact k-th largest pred among negatives ----
    unsigned prefix = 0;
    unsigned kk = (unsigned)k0;
    if (k0 > 0) {
        #pragma unroll 1
        for (int r = 0; r < 4; r++) {
            const int shift = 24 - 8 * r;
            // zero per-warp histograms
            unsigned* hflat = &s_hist[0][0];
            for (int i = tid; i < NWARPS * 256; i += NTHREADS) hflat[i] = 0;
            __syncthreads();

            for (int i = tid; i < NC; i += NTHREADS) {
                bool isneg = !((s_tbits[i >> 5] >> (i & 31)) & 1u);
                if (isneg) {
                    unsigned key = fkey(s_pred[i]);
                    bool match = (r == 0) || (((key ^ prefix) >> (shift + 8)) == 0u);
                    if (match)
                        atomicAdd(&s_hist[wid][(key >> shift) & 255u], 1u);
                }
            }
            __syncthreads();

            // reduce across warps
            unsigned tot = 0;
            #pragma unroll
            for (int w = 0; w < NWARPS; w++) tot += s_hist[w][tid];
            s_cnt[tid]  = tot;
            s_scan[tid] = tot;
            __syncthreads();

            // inclusive suffix scan: s_scan[b] = sum_{j>=b} cnt[j]
            #pragma unroll
            for (int off = 1; off < 256; off <<= 1) {
                unsigned v = s_scan[tid];
                if (tid + off < 256) v += s_scan[tid + off];
                __syncthreads();
                s_scan[tid] = v;
                __syncthreads();
            }

            // find bin b: strictly-above < kk <= inclusive
            unsigned incl  = s_scan[tid];
            unsigned above = incl - s_cnt[tid];
            if (incl >= kk && above < kk) {
                s_bsel = (unsigned)tid;
                s_krem = kk - above;
            }
            __syncthreads();
            prefix |= (s_bsel << shift);
            kk = s_krem;
            __syncthreads();
        }
    }
    const unsigned tkey = prefix;  // exact key of k-th largest negative pred
    const unsigned krem = kk;      // how many tied-at-threshold elements to include

    // ---- final pass: masked BCE sum ----
    float acc = 0.f;
    for (int i = tid; i < NC; i += NTHREADS) {
        float x = s_pred[i];
        bool isp = (s_tbits[i >> 5] >> (i & 31)) & 1u;
        if (isp) {
            acc += softplusf(x) - x;                 // target=1: softplus(x) - x
        } else if (k0 > 0 && fkey(x) > tkey) {
            acc += softplusf(x);                     // selected hard negative
        }
    }
    // block reduce
    #pragma unroll
    for (int o = 16; o; o >>= 1) acc += __shfl_down_sync(0xFFFFFFFFu, acc, o);
    if (lane == 0) s_red[wid] = acc;
    __syncthreads();
    if (tid == 0) {
        float total = 0.f;
        for (int w = 0; w < NWARPS; w++) total += s_red[w];
        if (k0 > 0) total += (float)krem * softplusf(kinv(tkey));  // tie correction (exact)
        atomicAdd(&g_loss, (double)total);
        atomicAdd(&g_tsum, (double)pos);
    }
}

__global__ void init_kernel() {
    g_loss = 0.0;
    g_tsum = 0.0;
}

__global__ void fin_kernel(float* out) {
    out[0] = (float)(g_loss / g_tsum);
}

extern "C" void kernel_launch(void* const* d_in, const int* in_sizes, int n_in,
                              void* d_out, int out_size) {
    const float* pred   = (const float*)d_in[0];
    const float* target = (const float*)d_in[1];
    float* out = (float*)d_out;

    int rows = in_sizes[0] / NC;

    init_kernel<<<1, 1>>>();
    hardneg_kernel<<<rows, NTHREADS>>>(pred, target);
    fin_kernel<<<1, 1>>>(out);
}

// round 2
// speedup vs baseline: 2.1564x; 2.1564x over previous
#include <cuda_runtime.h>

// N=8192 rows, C=5000 classes, RATIO=3
#define NC   5000
#define NT   256
#define NW   8
#define HW   2048   // histogram words: 4096 bins, two 16-bit counts per word
#define CAP  1024   // candidate capacity (expected ~50-120)

__device__ double g_loss;
__device__ double g_tsum;

// order-preserving float->uint key (larger float <-> larger key)
__device__ __forceinline__ unsigned fkey(float f) {
    unsigned b = __float_as_uint(f);
    return (b & 0x80000000u) ? ~b : (b | 0x80000000u);
}
__device__ __forceinline__ float kinv(unsigned k) {
    return __uint_as_float((k & 0x80000000u) ? (k & 0x7FFFFFFFu) : ~k);
}
// fast softplus (MUFU ex2/lg2 via fast math intrinsics)
__device__ __forceinline__ float sp(float x) {
    float l = __logf(1.f + __expf(-fabsf(x)));
    return x > 0.f ? x + l : l;
}

__global__ void __launch_bounds__(NT)
hardneg(const float* __restrict__ pred, const float* __restrict__ target) {
    __shared__ unsigned s_key[NC];     // 20000 B : keys (0 for positives)
    __shared__ unsigned s_hist[HW];    //  8192 B : packed 16-bit bin counts
    __shared__ unsigned s_cand[CAP];   //  4096 B : threshold-bin candidates
    __shared__ unsigned s_wsum[NW];
    __shared__ int      s_posr[NW];
    __shared__ float    s_accr[NW];
    __shared__ unsigned s_binv, s_kkv, s_tkey, s_krem;
    __shared__ int      s_cnt;

    const int tid  = threadIdx.x;
    const int lane = tid & 31;
    const int wid  = tid >> 5;
    const int row  = blockIdx.x;

    const float4* p4 = (const float4*)(pred   + (size_t)row * NC);
    const float4* t4 = (const float4*)(target + (size_t)row * NC);

    #pragma unroll
    for (int j = 0; j < HW / NT; j++) s_hist[tid + j * NT] = 0;
    if (tid == 0) s_cnt = 0;
    __syncthreads();

    // ---- pass A: load, classify, key, histogram, positive BCE ----
    int   poscnt = 0;
    float accP   = 0.f;
    uint4* k4s = (uint4*)s_key;

    #define PROC(px, tx, kout)                                             \
        do {                                                               \
            float _x = (px);                                               \
            if ((tx) != 0.f) {                                             \
                poscnt++; accP += sp(_x) - _x; (kout) = 0u;                \
            } else {                                                       \
                unsigned _k = fkey(_x); (kout) = _k;                       \
                atomicAdd(&s_hist[_k >> 21],                               \
                          ((_k >> 20) & 1u) ? 65536u : 1u);                \
            }                                                              \
        } while (0)

    for (int i = tid; i < NC / 4; i += NT) {
        float4 p = p4[i];
        float4 t = t4[i];
        uint4  k;
        PROC(p.x, t.x, k.x);
        PROC(p.y, t.y, k.y);
        PROC(p.z, t.z, k.z);
        PROC(p.w, t.w, k.w);
        k4s[i] = k;
    }
    #undef PROC
    __syncthreads();

    // ---- locate threshold bin: suffix counts via shuffle scan ----
    // thread t owns bins [t*16, t*16+16) = words [t*8, t*8+8)
    unsigned w8[8];
    unsigned S = 0;
    #pragma unroll
    for (int j = 0; j < 8; j++) {
        unsigned v = s_hist[tid * 8 + j];
        w8[j] = v;
        S += (v & 0xFFFFu) + (v >> 16);
    }
    unsigned v = S;  // inclusive suffix within warp
    #pragma unroll
    for (int off = 1; off < 32; off <<= 1) {
        unsigned o = __shfl_down_sync(0xFFFFFFFFu, v, off);
        if (lane + off < 32) v += o;
    }
    if (lane == 0) s_wsum[wid] = v;

    int pc = poscnt;
    #pragma unroll
    for (int off = 16; off; off >>= 1) pc += __shfl_down_sync(0xFFFFFFFFu, pc, off);
    if (lane == 0) s_posr[wid] = pc;
    __syncthreads();

    int post = 0;
    #pragma unroll
    for (int k = 0; k < NW; k++) post += s_posr[k];
    int k0 = 3 * post;
    if (k0 > NC - post) k0 = NC - post;

    unsigned above = v - S;  // bins above mine within my warp
    #pragma unroll
    for (int k = wid + 1; k < NW; k++) above += s_wsum[k];

    if (k0 > 0) {
        unsigned kk = (unsigned)k0;
        if (above < kk && kk <= above + S) {
            unsigned a = above;
            for (int j = 15; j >= 0; j--) {   // walk my 16 bins from the top
                unsigned wv = w8[j >> 1];
                unsigned c  = (j & 1) ? (wv >> 16) : (wv & 0xFFFFu);
                if (kk <= a + c) { s_binv = (unsigned)(tid * 16 + j); s_kkv = kk - a; break; }
                a += c;
            }
        }
    }
    __syncthreads();

    // ---- gather candidates from the threshold bin ----
    if (k0 > 0) {
        unsigned bsel = s_binv;
        const uint4* kr = (const uint4*)s_key;
        #define G(kc)                                                          \
            if (((kc) >> 20) == bsel) {                                        \
                int s = atomicAdd(&s_cnt, 1);                                  \
                if (s < CAP) s_cand[s] = (kc);                                 \
            }
        for (int i = tid; i < NC / 4; i += NT) {
            uint4 kv = kr[i];
            G(kv.x) G(kv.y) G(kv.z) G(kv.w)
        }
        #undef G
    }
    __syncthreads();

    // ---- exact k-th largest among candidates (rank counting) ----
    if (k0 > 0) {
        int M = s_cnt; if (M > CAP) M = CAP;
        unsigned kk = s_kkv;
        for (int c = tid; c < M; c += NT) {
            unsigned key = s_cand[c];
            unsigned gt = 0, eq = 0;
            for (int j = 0; j < M; j++) {
                unsigned o = s_cand[j];
                gt += (o > key);
                eq += (o == key);
            }
            if (gt < kk && kk <= gt + eq) { s_tkey = key; s_krem = kk - gt; }
        }
    }
    __syncthreads();

    // ---- final pass: sum softplus over selected hard negatives ----
    float acc = accP;
    if (k0 > 0) {
        unsigned tk = s_tkey;
        const uint4* kr = (const uint4*)s_key;
        for (int i = tid; i < NC / 4; i += NT) {
            uint4 kv = kr[i];
            if (kv.x > tk) acc += sp(kinv(kv.x));
            if (kv.y > tk) acc += sp(kinv(kv.y));
            if (kv.z > tk) acc += sp(kinv(kv.z));
            if (kv.w > tk) acc += sp(kinv(kv.w));
        }
    }
    #pragma unroll
    for (int off = 16; off; off >>= 1) acc += __shfl_down_sync(0xFFFFFFFFu, acc, off);
    if (lane == 0) s_accr[wid] = acc;
    __syncthreads();

    if (tid == 0) {
        float tot = 0.f;
        #pragma unroll
        for (int k = 0; k < NW; k++) tot += s_accr[k];
        if (k0 > 0) tot += (float)s_krem * sp(kinv(s_tkey));  // exact tie correction
        atomicAdd(&g_loss, (double)tot);
        atomicAdd(&g_tsum, (double)post);
    }
}

__global__ void init_kernel() { g_loss = 0.0; g_tsum = 0.0; }
__global__ void fin_kernel(float* out) { out[0] = (float)(g_loss / g_tsum); }

extern "C" void kernel_launch(void* const* d_in, const int* in_sizes, int n_in,
                              void* d_out, int out_size) {
    const float* pred   = (const float*)d_in[0];
    const float* target = (const float*)d_in[1];
    float* out = (float*)d_out;
    int rows = in_sizes[0] / NC;

    init_kernel<<<1, 1>>>();
    hardneg<<<rows, NT>>>(pred, target);
    fin_kernel<<<1, 1>>>(out);
}